// round 1
// baseline (speedup 1.0000x reference)
#include <cuda_runtime.h>
#include <cstddef>

// Problem constants
#define BB 2
#define SS 2048
#define DD 1024
#define HH 16
#define HDIM 64

// Scratch (no cudaMalloc allowed)
__device__ float g_qkv[BB * SS * 3 * DD];   // [B,S,3,H,HD] flattened = [4096, 3072]
__device__ float g_attn[BB * SS * DD];      // [B,S,D]

// ---------------------------------------------------------------------------
// SGEMM: C[M,N] = A[M,K] * B[N,K]^T   (both row-major, weights are [out,in])
// 128x128 tile, BK=16, 256 threads, 8x8 per thread.
// ---------------------------------------------------------------------------
__global__ __launch_bounds__(256) void sgemm_nt(const float* __restrict__ A,
                                                const float* __restrict__ Bw,
                                                float* __restrict__ C,
                                                int M, int N, int K) {
    __shared__ float As[16][128];
    __shared__ float Bs[16][128];
    const int tid = threadIdx.x;
    const int tr = tid >> 4;   // 0..15 (row group)
    const int tc = tid & 15;   // 0..15 (col group)
    const int rowBase = blockIdx.y * 128;
    const int colBase = blockIdx.x * 128;

    float acc[8][8];
#pragma unroll
    for (int i = 0; i < 8; ++i)
#pragma unroll
        for (int j = 0; j < 8; ++j) acc[i][j] = 0.f;

    for (int k0 = 0; k0 < K; k0 += 16) {
#pragma unroll
        for (int t = 0; t < 2; ++t) {
            int f = tid + t * 256;          // 0..511
            int r = f >> 2;                 // 0..127
            int kc = (f & 3) << 2;          // 0,4,8,12
            float4 va = *(const float4*)&A[(size_t)(rowBase + r) * K + k0 + kc];
            As[kc + 0][r] = va.x; As[kc + 1][r] = va.y;
            As[kc + 2][r] = va.z; As[kc + 3][r] = va.w;
            float4 vb = *(const float4*)&Bw[(size_t)(colBase + r) * K + k0 + kc];
            Bs[kc + 0][r] = vb.x; Bs[kc + 1][r] = vb.y;
            Bs[kc + 2][r] = vb.z; Bs[kc + 3][r] = vb.w;
        }
        __syncthreads();
#pragma unroll
        for (int kk = 0; kk < 16; ++kk) {
            float ra[8], rb[8];
            *(float4*)&ra[0] = *(const float4*)&As[kk][tr * 8];
            *(float4*)&ra[4] = *(const float4*)&As[kk][tr * 8 + 4];
            *(float4*)&rb[0] = *(const float4*)&Bs[kk][tc * 8];
            *(float4*)&rb[4] = *(const float4*)&Bs[kk][tc * 8 + 4];
#pragma unroll
            for (int i = 0; i < 8; ++i)
#pragma unroll
                for (int j = 0; j < 8; ++j)
                    acc[i][j] += ra[i] * rb[j];
        }
        __syncthreads();
    }

#pragma unroll
    for (int i = 0; i < 8; ++i) {
        int r = rowBase + tr * 8 + i;
#pragma unroll
        for (int j = 0; j < 8; j += 4) {
            float4 v = make_float4(acc[i][j], acc[i][j + 1], acc[i][j + 2], acc[i][j + 3]);
            *(float4*)&C[(size_t)r * N + colBase + tc * 8 + j] = v;
        }
    }
}

// ---------------------------------------------------------------------------
// Flash attention (fp32, online softmax).
// Block: one (b, h, q-tile of 128). 256 threads.
// Thread owns 4 q-rows x 8 cols. Padded smem (+1) to avoid bank conflicts.
// ---------------------------------------------------------------------------
#define BQ 128
#define BKV 64
#define QPAD 65
#define ATTN_SMEM ((BQ * QPAD + BKV * QPAD + BKV * QPAD + BQ * QPAD) * 4)

__global__ __launch_bounds__(256) void attn_kernel(const float* __restrict__ qkv,
                                                   float* __restrict__ out) {
    extern __shared__ float sm[];
    float* Qs = sm;                         // [128][65]
    float* Ks = Qs + BQ * QPAD;             // [64][65]
    float* Vs = Ks + BKV * QPAD;            // [64][65]
    float* Ps = Vs + BKV * QPAD;            // [128][65]

    const int tid = threadIdx.x;
    const int tr = tid >> 3;   // 0..31, owns q rows tr*4 .. tr*4+3
    const int tc = tid & 7;    // 0..7, owns 8 cols tc*8 .. tc*8+7
    const int b = blockIdx.z, h = blockIdx.y;
    const int q0 = blockIdx.x * BQ;
    const float scale = 0.125f;  // 1/sqrt(64)

    // Load Q tile [128 x 64]
#pragma unroll
    for (int t = 0; t < 8; ++t) {
        int f = tid + t * 256;          // 0..2047
        int r = f >> 4;                 // 0..127
        int dc = (f & 15) << 2;         // 0..60
        const float* src = &qkv[(((size_t)(b * SS + q0 + r)) * 3 + 0) * DD + h * HDIM + dc];
        float4 v = *(const float4*)src;
        float* dst = &Qs[r * QPAD + dc];
        dst[0] = v.x; dst[1] = v.y; dst[2] = v.z; dst[3] = v.w;
    }

    float m[4], l[4], acc[4][8];
#pragma unroll
    for (int i = 0; i < 4; ++i) {
        m[i] = -1e30f; l[i] = 0.f;
#pragma unroll
        for (int j = 0; j < 8; ++j) acc[i][j] = 0.f;
    }

    for (int kv0 = 0; kv0 < SS; kv0 += BKV) {
        __syncthreads();  // protect Ks/Vs (prev PV) and Q first iter
        // Load K,V tiles [64 x 64]
#pragma unroll
        for (int t = 0; t < 4; ++t) {
            int f = tid + t * 256;       // 0..1023
            int r = f >> 4;              // 0..63
            int dc = (f & 15) << 2;
            size_t base = ((size_t)(b * SS + kv0 + r)) * 3;
            float4 kf = *(const float4*)&qkv[(base + 1) * DD + h * HDIM + dc];
            float* dk = &Ks[r * QPAD + dc];
            dk[0] = kf.x; dk[1] = kf.y; dk[2] = kf.z; dk[3] = kf.w;
            float4 vf = *(const float4*)&qkv[(base + 2) * DD + h * HDIM + dc];
            float* dv = &Vs[r * QPAD + dc];
            dv[0] = vf.x; dv[1] = vf.y; dv[2] = vf.z; dv[3] = vf.w;
        }
        __syncthreads();

        // S = Q @ K^T  (per-thread 4x8)
        float s[4][8];
#pragma unroll
        for (int i = 0; i < 4; ++i)
#pragma unroll
            for (int c = 0; c < 8; ++c) s[i][c] = 0.f;

#pragma unroll 4
        for (int d = 0; d < HDIM; ++d) {
            float rq[4], rk[8];
#pragma unroll
            for (int i = 0; i < 4; ++i) rq[i] = Qs[(tr * 4 + i) * QPAD + d];
#pragma unroll
            for (int c = 0; c < 8; ++c) rk[c] = Ks[(tc * 8 + c) * QPAD + d];
#pragma unroll
            for (int i = 0; i < 4; ++i)
#pragma unroll
                for (int c = 0; c < 8; ++c)
                    s[i][c] += rq[i] * rk[c];
        }

        // Online softmax update, write P to smem
#pragma unroll
        for (int i = 0; i < 4; ++i) {
            float tmax = -1e30f;
#pragma unroll
            for (int c = 0; c < 8; ++c) { s[i][c] *= scale; tmax = fmaxf(tmax, s[i][c]); }
            tmax = fmaxf(tmax, __shfl_xor_sync(0xffffffffu, tmax, 1));
            tmax = fmaxf(tmax, __shfl_xor_sync(0xffffffffu, tmax, 2));
            tmax = fmaxf(tmax, __shfl_xor_sync(0xffffffffu, tmax, 4));
            float mn = fmaxf(m[i], tmax);
            float alpha = __expf(m[i] - mn);
            m[i] = mn;
            float rsum = 0.f;
#pragma unroll
            for (int c = 0; c < 8; ++c) {
                float p = __expf(s[i][c] - mn);
                Ps[(tr * 4 + i) * QPAD + tc * 8 + c] = p;
                rsum += p;
            }
            rsum += __shfl_xor_sync(0xffffffffu, rsum, 1);
            rsum += __shfl_xor_sync(0xffffffffu, rsum, 2);
            rsum += __shfl_xor_sync(0xffffffffu, rsum, 4);
            l[i] = l[i] * alpha + rsum;
#pragma unroll
            for (int j = 0; j < 8; ++j) acc[i][j] *= alpha;
        }
        __syncthreads();

        // O += P @ V  (per-thread 4x8, d cols = tc*8+j)
#pragma unroll 4
        for (int kv = 0; kv < BKV; ++kv) {
            float rp[4], rv[8];
#pragma unroll
            for (int i = 0; i < 4; ++i) rp[i] = Ps[(tr * 4 + i) * QPAD + kv];
#pragma unroll
            for (int j = 0; j < 8; ++j) rv[j] = Vs[kv * QPAD + tc * 8 + j];
#pragma unroll
            for (int i = 0; i < 4; ++i)
#pragma unroll
                for (int j = 0; j < 8; ++j)
                    acc[i][j] += rp[i] * rv[j];
        }
    }

    // Epilogue: O / l  -> g_attn[b, q, h*64 + d]
#pragma unroll
    for (int i = 0; i < 4; ++i) {
        float inv = 1.0f / l[i];
        int q = q0 + tr * 4 + i;
        float* dst = &out[((size_t)(b * SS + q)) * DD + h * HDIM + tc * 8];
#pragma unroll
        for (int j = 0; j < 8; j += 4) {
            float4 v = make_float4(acc[i][j] * inv, acc[i][j + 1] * inv,
                                   acc[i][j + 2] * inv, acc[i][j + 3] * inv);
            *(float4*)&dst[j] = v;
        }
    }
}

// ---------------------------------------------------------------------------
// Launch
// ---------------------------------------------------------------------------
extern "C" void kernel_launch(void* const* d_in, const int* in_sizes, int n_in,
                              void* d_out, int out_size) {
    const float* x     = (const float*)d_in[0];   // [2,2048,1024]
    const float* w_qkv = (const float*)d_in[1];   // [3072,1024]
    const float* w_out = (const float*)d_in[2];   // [1024,1024]
    float* out = (float*)d_out;                   // [2,2048,1024]

    void* p;
    cudaGetSymbolAddress(&p, g_qkv);
    float* qkv = (float*)p;
    cudaGetSymbolAddress(&p, g_attn);
    float* attn = (float*)p;

    // 1) QKV projection: [4096,1024] @ [3072,1024]^T -> [4096,3072]
    {
        dim3 grid(3072 / 128, (BB * SS) / 128);
        sgemm_nt<<<grid, 256>>>(x, w_qkv, qkv, BB * SS, 3 * DD, DD);
    }

    // 2) Attention
    {
        cudaFuncSetAttribute(attn_kernel, cudaFuncAttributeMaxDynamicSharedMemorySize,
                             ATTN_SMEM);
        dim3 grid(SS / BQ, HH, BB);
        attn_kernel<<<grid, 256, ATTN_SMEM>>>(qkv, attn);
    }

    // 3) Output projection: [4096,1024] @ [1024,1024]^T -> [4096,1024]
    {
        dim3 grid(DD / 128, (BB * SS) / 128);
        sgemm_nt<<<grid, 256>>>(attn, w_out, out, BB * SS, DD, DD);
    }
}

// round 3
// speedup vs baseline: 1.3204x; 1.3204x over previous
#include <cuda_runtime.h>
#include <cuda_bf16.h>
#include <cstdint>
#include <cstddef>

// Problem constants
#define BB 2
#define SS 2048
#define DD 1024
#define HH 16
#define HDIM 64
#define KDIM 1024

// Scratch (no cudaMalloc allowed)
__device__ float g_qkv[BB * SS * 3 * DD];   // [4096, 3072] fp32
__device__ float g_attn[BB * SS * DD];      // [4096, 1024] fp32
__device__ __nv_bfloat16 g_xhi[BB * SS * DD],  g_xlo[BB * SS * DD];
__device__ __nv_bfloat16 g_whi[3 * DD * DD],   g_wlo[3 * DD * DD];
__device__ __nv_bfloat16 g_ohi[DD * DD],       g_olo[DD * DD];
__device__ __nv_bfloat16 g_ahi[BB * SS * DD],  g_alo[BB * SS * DD];

// ---------------------------------------------------------------------------
// Baseline-PTX helpers (NO sm_103a-only instructions — harness compiles
// via compute_103 virtual arch, so tcgen05/TMA-tensor are unavailable).
// ---------------------------------------------------------------------------
__device__ __forceinline__ uint32_t smem_u32(const void* p) {
    uint32_t a;
    asm("{ .reg .u64 t; cvta.to.shared.u64 t, %1; cvt.u32.u64 %0, t; }"
        : "=r"(a) : "l"(p));
    return a;
}

__device__ __forceinline__ void cp16(uint32_t dst, const void* src) {
    asm volatile("cp.async.ca.shared.global [%0], [%1], 16;"
                 :: "r"(dst), "l"(src) : "memory");
}
#define CP_COMMIT() asm volatile("cp.async.commit_group;" ::: "memory")
#define CP_WAIT(n)  asm volatile("cp.async.wait_group %0;" :: "n"(n) : "memory")

__device__ __forceinline__ void ldsm4(uint32_t& r0, uint32_t& r1,
                                      uint32_t& r2, uint32_t& r3, uint32_t a) {
    asm volatile("ldmatrix.sync.aligned.m8n8.x4.shared.b16 {%0,%1,%2,%3}, [%4];"
                 : "=r"(r0), "=r"(r1), "=r"(r2), "=r"(r3) : "r"(a));
}

__device__ __forceinline__ void mma16816(float* c, const uint32_t* a,
                                         uint32_t b0, uint32_t b1) {
    asm volatile(
        "mma.sync.aligned.m16n8k16.row.col.f32.bf16.bf16.f32 "
        "{%0,%1,%2,%3}, {%4,%5,%6,%7}, {%8,%9}, {%0,%1,%2,%3};"
        : "+f"(c[0]), "+f"(c[1]), "+f"(c[2]), "+f"(c[3])
        : "r"(a[0]), "r"(a[1]), "r"(a[2]), "r"(a[3]), "r"(b0), "r"(b1));
}

// ---------------------------------------------------------------------------
// fp32 -> bf16 hi/lo split
// ---------------------------------------------------------------------------
__global__ __launch_bounds__(256) void split_kernel(const float* __restrict__ s,
                                                    __nv_bfloat16* __restrict__ hi,
                                                    __nv_bfloat16* __restrict__ lo,
                                                    int n4) {
    int i = blockIdx.x * blockDim.x + threadIdx.x;
    if (i >= n4) return;
    float4 v = ((const float4*)s)[i];
    __nv_bfloat16 h0 = __float2bfloat16(v.x);
    __nv_bfloat16 h1 = __float2bfloat16(v.y);
    __nv_bfloat16 h2 = __float2bfloat16(v.z);
    __nv_bfloat16 h3 = __float2bfloat16(v.w);
    __nv_bfloat16 l0 = __float2bfloat16(v.x - __bfloat162float(h0));
    __nv_bfloat16 l1 = __float2bfloat16(v.y - __bfloat162float(h1));
    __nv_bfloat16 l2 = __float2bfloat16(v.z - __bfloat162float(h2));
    __nv_bfloat16 l3 = __float2bfloat16(v.w - __bfloat162float(h3));
    ((__nv_bfloat162*)hi)[2 * i]     = __halves2bfloat162(h0, h1);
    ((__nv_bfloat162*)hi)[2 * i + 1] = __halves2bfloat162(h2, h3);
    ((__nv_bfloat162*)lo)[2 * i]     = __halves2bfloat162(l0, l1);
    ((__nv_bfloat162*)lo)[2 * i + 1] = __halves2bfloat162(l2, l3);
}

// ---------------------------------------------------------------------------
// Split-bf16 HMMA GEMM: C[M,N] = A[M,K] @ B[N,K]^T (fp32-accurate)
// CTA tile 128x128, BK=32, 8 warps (4M x 2N), warp tile 32x64.
// cp.async double-buffered smem; rows padded to 40 bf16 (80B) -> conflict-free
// ldmatrix (bank starts {0,20,8,28,16,4,24,12} cover all 32 banks).
// ---------------------------------------------------------------------------
#define ROWP 40
#define ARR_BYTES (128 * ROWP * 2)       // 10240
#define STAGE_BYTES (4 * ARR_BYTES)      // 40960: Ahi, Alo, Bhi, Blo
#define GT_SMEM_TOTAL (2 * STAGE_BYTES)  // 81920

__global__ __launch_bounds__(256) void tc_gemm(const __nv_bfloat16* __restrict__ Ahi,
                                               const __nv_bfloat16* __restrict__ Alo,
                                               const __nv_bfloat16* __restrict__ Bhi,
                                               const __nv_bfloat16* __restrict__ Blo,
                                               float* __restrict__ C,
                                               int N, int K) {
    extern __shared__ char smem_raw[];
    const uint32_t sb = smem_u32(smem_raw);
    const int tid = threadIdx.x;
    const int lane = tid & 31;
    const int warp = tid >> 5;
    const int wm = warp & 3;          // M warp: rows wm*32
    const int wn = warp >> 2;         // N warp: cols wn*64
    const int rowBase = blockIdx.y * 128;
    const int colBase = blockIdx.x * 128;

    const __nv_bfloat16* srcs[4] = {
        Ahi + (size_t)rowBase * K, Alo + (size_t)rowBase * K,
        Bhi + (size_t)colBase * K, Blo + (size_t)colBase * K };

    float acc[2][8][4];
#pragma unroll
    for (int mt = 0; mt < 2; ++mt)
#pragma unroll
        for (int nt = 0; nt < 8; ++nt)
#pragma unroll
            for (int r = 0; r < 4; ++r) acc[mt][nt][r] = 0.f;

    const int nstages = K >> 5;  // 32

    // Loader lambda-equivalent (macro-free, inlined)
    auto load_stage = [&](int c, int st) {
        const int k0 = c << 5;
#pragma unroll
        for (int arr = 0; arr < 4; ++arr) {
            const __nv_bfloat16* s = srcs[arr];
            uint32_t dbase = sb + st * STAGE_BYTES + arr * ARR_BYTES;
#pragma unroll
            for (int p = 0; p < 2; ++p) {
                int f = tid + p * 256;
                int r = f >> 2, kc = f & 3;
                cp16(dbase + (uint32_t)(r * ROWP + kc * 8) * 2,
                     s + (size_t)r * K + k0 + kc * 8);
            }
        }
    };

    // ldmatrix address components
    const int arow = wm * 32 + (lane & 15);
    const int acolH = (lane >> 4) * 8;
    const int browIn = (lane & 7) + ((lane & 16) >> 1);
    const int bcolH = ((lane >> 3) & 1) * 8;

    load_stage(0, 0);
    CP_COMMIT();

    for (int c = 0; c < nstages; ++c) {
        const int st = c & 1;
        if (c + 1 < nstages) {
            load_stage(c + 1, (c + 1) & 1);
            CP_COMMIT();
            CP_WAIT(1);
        } else {
            CP_WAIT(0);
        }
        __syncthreads();

        uint32_t aHi = sb + st * STAGE_BYTES;
        uint32_t aLo = aHi + ARR_BYTES;
        uint32_t bHi = aHi + 2 * ARR_BYTES;
        uint32_t bLo = aHi + 3 * ARR_BYTES;

#pragma unroll
        for (int ks = 0; ks < 2; ++ks) {
            uint32_t ah[2][4], al[2][4];
#pragma unroll
            for (int mt = 0; mt < 2; ++mt) {
                uint32_t off = (uint32_t)((arow + mt * 16) * ROWP + ks * 16 + acolH) * 2;
                ldsm4(ah[mt][0], ah[mt][1], ah[mt][2], ah[mt][3], aHi + off);
                ldsm4(al[mt][0], al[mt][1], al[mt][2], al[mt][3], aLo + off);
            }
            uint32_t bh[4][4], bl[4][4];
#pragma unroll
            for (int nt2 = 0; nt2 < 4; ++nt2) {
                int row = wn * 64 + nt2 * 16 + browIn;
                uint32_t off = (uint32_t)(row * ROWP + ks * 16 + bcolH) * 2;
                ldsm4(bh[nt2][0], bh[nt2][1], bh[nt2][2], bh[nt2][3], bHi + off);
                ldsm4(bl[nt2][0], bl[nt2][1], bl[nt2][2], bl[nt2][3], bLo + off);
            }
#pragma unroll
            for (int mt = 0; mt < 2; ++mt)
#pragma unroll
                for (int nt = 0; nt < 8; ++nt) {
                    int nt2 = nt >> 1, pb = (nt & 1) * 2;
                    mma16816(acc[mt][nt], ah[mt], bh[nt2][pb], bh[nt2][pb + 1]);
                    mma16816(acc[mt][nt], ah[mt], bl[nt2][pb], bl[nt2][pb + 1]);
                    mma16816(acc[mt][nt], al[mt], bh[nt2][pb], bh[nt2][pb + 1]);
                }
        }
        __syncthreads();
    }

    // Epilogue: direct fp32 stores
#pragma unroll
    for (int mt = 0; mt < 2; ++mt) {
        int row0 = rowBase + wm * 32 + mt * 16 + (lane >> 2);
#pragma unroll
        for (int nt = 0; nt < 8; ++nt) {
            int col = colBase + wn * 64 + nt * 8 + (lane & 3) * 2;
            *(float2*)&C[(size_t)row0 * N + col] =
                make_float2(acc[mt][nt][0], acc[mt][nt][1]);
            *(float2*)&C[(size_t)(row0 + 8) * N + col] =
                make_float2(acc[mt][nt][2], acc[mt][nt][3]);
        }
    }
}

// ---------------------------------------------------------------------------
// Flash attention (fp32, online softmax) — unchanged (known good)
// ---------------------------------------------------------------------------
#define BQ 128
#define BKV 64
#define QPAD 65
#define ATTN_SMEM ((BQ * QPAD + BKV * QPAD + BKV * QPAD + BQ * QPAD) * 4)

__global__ __launch_bounds__(256) void attn_kernel(const float* __restrict__ qkv,
                                                   float* __restrict__ out) {
    extern __shared__ char smem_raw[];
    float* sm = (float*)smem_raw;
    float* Qs = sm;
    float* Ks = Qs + BQ * QPAD;
    float* Vs = Ks + BKV * QPAD;
    float* Ps = Vs + BKV * QPAD;

    const int tid = threadIdx.x;
    const int tr = tid >> 3;
    const int tc = tid & 7;
    const int b = blockIdx.z, h = blockIdx.y;
    const int q0 = blockIdx.x * BQ;
    const float scale = 0.125f;

#pragma unroll
    for (int t = 0; t < 8; ++t) {
        int f = tid + t * 256;
        int r = f >> 4;
        int dc = (f & 15) << 2;
        const float* src = &qkv[(((size_t)(b * SS + q0 + r)) * 3 + 0) * DD + h * HDIM + dc];
        float4 v = *(const float4*)src;
        float* dst = &Qs[r * QPAD + dc];
        dst[0] = v.x; dst[1] = v.y; dst[2] = v.z; dst[3] = v.w;
    }

    float m[4], l[4], acc[4][8];
#pragma unroll
    for (int i = 0; i < 4; ++i) {
        m[i] = -1e30f; l[i] = 0.f;
#pragma unroll
        for (int j = 0; j < 8; ++j) acc[i][j] = 0.f;
    }

    for (int kv0 = 0; kv0 < SS; kv0 += BKV) {
        __syncthreads();
#pragma unroll
        for (int t = 0; t < 4; ++t) {
            int f = tid + t * 256;
            int r = f >> 4;
            int dc = (f & 15) << 2;
            size_t base = ((size_t)(b * SS + kv0 + r)) * 3;
            float4 kf = *(const float4*)&qkv[(base + 1) * DD + h * HDIM + dc];
            float* dk = &Ks[r * QPAD + dc];
            dk[0] = kf.x; dk[1] = kf.y; dk[2] = kf.z; dk[3] = kf.w;
            float4 vf = *(const float4*)&qkv[(base + 2) * DD + h * HDIM + dc];
            float* dv = &Vs[r * QPAD + dc];
            dv[0] = vf.x; dv[1] = vf.y; dv[2] = vf.z; dv[3] = vf.w;
        }
        __syncthreads();

        float s[4][8];
#pragma unroll
        for (int i = 0; i < 4; ++i)
#pragma unroll
            for (int c = 0; c < 8; ++c) s[i][c] = 0.f;

#pragma unroll 4
        for (int d = 0; d < HDIM; ++d) {
            float rq[4], rk[8];
#pragma unroll
            for (int i = 0; i < 4; ++i) rq[i] = Qs[(tr * 4 + i) * QPAD + d];
#pragma unroll
            for (int c = 0; c < 8; ++c) rk[c] = Ks[(tc * 8 + c) * QPAD + d];
#pragma unroll
            for (int i = 0; i < 4; ++i)
#pragma unroll
                for (int c = 0; c < 8; ++c)
                    s[i][c] += rq[i] * rk[c];
        }

#pragma unroll
        for (int i = 0; i < 4; ++i) {
            float tmax = -1e30f;
#pragma unroll
            for (int c = 0; c < 8; ++c) { s[i][c] *= scale; tmax = fmaxf(tmax, s[i][c]); }
            tmax = fmaxf(tmax, __shfl_xor_sync(0xffffffffu, tmax, 1));
            tmax = fmaxf(tmax, __shfl_xor_sync(0xffffffffu, tmax, 2));
            tmax = fmaxf(tmax, __shfl_xor_sync(0xffffffffu, tmax, 4));
            float mn = fmaxf(m[i], tmax);
            float alpha = __expf(m[i] - mn);
            m[i] = mn;
            float rsum = 0.f;
#pragma unroll
            for (int c = 0; c < 8; ++c) {
                float p = __expf(s[i][c] - mn);
                Ps[(tr * 4 + i) * QPAD + tc * 8 + c] = p;
                rsum += p;
            }
            rsum += __shfl_xor_sync(0xffffffffu, rsum, 1);
            rsum += __shfl_xor_sync(0xffffffffu, rsum, 2);
            rsum += __shfl_xor_sync(0xffffffffu, rsum, 4);
            l[i] = l[i] * alpha + rsum;
#pragma unroll
            for (int j = 0; j < 8; ++j) acc[i][j] *= alpha;
        }
        __syncthreads();

#pragma unroll 4
        for (int kv = 0; kv < BKV; ++kv) {
            float rp[4], rv[8];
#pragma unroll
            for (int i = 0; i < 4; ++i) rp[i] = Ps[(tr * 4 + i) * QPAD + kv];
#pragma unroll
            for (int j = 0; j < 8; ++j) rv[j] = Vs[kv * QPAD + tc * 8 + j];
#pragma unroll
            for (int i = 0; i < 4; ++i)
#pragma unroll
                for (int j = 0; j < 8; ++j)
                    acc[i][j] += rp[i] * rv[j];
        }
    }

#pragma unroll
    for (int i = 0; i < 4; ++i) {
        float inv = 1.0f / l[i];
        int q = q0 + tr * 4 + i;
        float* dst = &out[((size_t)(b * SS + q)) * DD + h * HDIM + tc * 8];
#pragma unroll
        for (int j = 0; j < 8; j += 4) {
            float4 v = make_float4(acc[i][j] * inv, acc[i][j + 1] * inv,
                                   acc[i][j + 2] * inv, acc[i][j + 3] * inv);
            *(float4*)&dst[j] = v;
        }
    }
}

// ---------------------------------------------------------------------------
// Launch
// ---------------------------------------------------------------------------
extern "C" void kernel_launch(void* const* d_in, const int* in_sizes, int n_in,
                              void* d_out, int out_size) {
    const float* x     = (const float*)d_in[0];   // [2,2048,1024]
    const float* w_qkv = (const float*)d_in[1];   // [3072,1024]
    const float* w_out = (const float*)d_in[2];   // [1024,1024]
    float* out = (float*)d_out;

    void* p;
    cudaGetSymbolAddress(&p, g_qkv);  float* qkv  = (float*)p;
    cudaGetSymbolAddress(&p, g_attn); float* attn = (float*)p;
    __nv_bfloat16 *xhi, *xlo, *whi, *wlo, *ohi, *olo, *ahi, *alo;
    cudaGetSymbolAddress(&p, g_xhi); xhi = (__nv_bfloat16*)p;
    cudaGetSymbolAddress(&p, g_xlo); xlo = (__nv_bfloat16*)p;
    cudaGetSymbolAddress(&p, g_whi); whi = (__nv_bfloat16*)p;
    cudaGetSymbolAddress(&p, g_wlo); wlo = (__nv_bfloat16*)p;
    cudaGetSymbolAddress(&p, g_ohi); ohi = (__nv_bfloat16*)p;
    cudaGetSymbolAddress(&p, g_olo); olo = (__nv_bfloat16*)p;
    cudaGetSymbolAddress(&p, g_ahi); ahi = (__nv_bfloat16*)p;
    cudaGetSymbolAddress(&p, g_alo); alo = (__nv_bfloat16*)p;

    cudaFuncSetAttribute(tc_gemm, cudaFuncAttributeMaxDynamicSharedMemorySize,
                         GT_SMEM_TOTAL);
    cudaFuncSetAttribute(attn_kernel, cudaFuncAttributeMaxDynamicSharedMemorySize,
                         ATTN_SMEM);

    // 0) Split inputs/weights into bf16 hi/lo
    {
        int n4x = (BB * SS * DD) / 4;
        split_kernel<<<(n4x + 255) / 256, 256>>>(x, xhi, xlo, n4x);
        int n4w = (3 * DD * DD) / 4;
        split_kernel<<<(n4w + 255) / 256, 256>>>(w_qkv, whi, wlo, n4w);
        int n4o = (DD * DD) / 4;
        split_kernel<<<(n4o + 255) / 256, 256>>>(w_out, ohi, olo, n4o);
    }

    // 1) QKV projection: [4096,1024] @ [3072,1024]^T -> [4096,3072]
    {
        dim3 grid(3 * DD / 128, (BB * SS) / 128);
        tc_gemm<<<grid, 256, GT_SMEM_TOTAL>>>(xhi, xlo, whi, wlo, qkv, 3 * DD, KDIM);
    }

    // 2) Attention (fp32 flash)
    {
        dim3 grid(SS / BQ, HH, BB);
        attn_kernel<<<grid, 256, ATTN_SMEM>>>(qkv, attn);
    }

    // 3) Split attention output, then output projection
    {
        int n4a = (BB * SS * DD) / 4;
        split_kernel<<<(n4a + 255) / 256, 256>>>(attn, ahi, alo, n4a);
        dim3 grid(DD / 128, (BB * SS) / 128);
        tc_gemm<<<grid, 256, GT_SMEM_TOTAL>>>(ahi, alo, ohi, olo, out, DD, KDIM);
    }
}

// round 4
// speedup vs baseline: 3.4765x; 2.6330x over previous
#include <cuda_runtime.h>
#include <cuda_bf16.h>
#include <cstdint>
#include <cstddef>

// Problem constants
#define BB 2
#define SS 2048
#define DD 1024
#define HH 16
#define HDIM 64
#define KDIM 1024

// Scratch (no cudaMalloc allowed)
__device__ float g_qkv[BB * SS * 3 * DD];   // [4096, 3072] fp32
__device__ __nv_bfloat16 g_xhi[BB * SS * DD],  g_xlo[BB * SS * DD];
__device__ __nv_bfloat16 g_whi[3 * DD * DD],   g_wlo[3 * DD * DD];
__device__ __nv_bfloat16 g_ohi[DD * DD],       g_olo[DD * DD];
__device__ __nv_bfloat16 g_ahi[BB * SS * DD],  g_alo[BB * SS * DD];
// Attention-ready layouts
__device__ __nv_bfloat16 g_qhi[BB * HH * SS * HDIM], g_qlo[BB * HH * SS * HDIM];
__device__ __nv_bfloat16 g_khi[BB * HH * SS * HDIM], g_klo[BB * HH * SS * HDIM];
__device__ __nv_bfloat16 g_vthi[BB * HH * HDIM * SS], g_vtlo[BB * HH * HDIM * SS];

// ---------------------------------------------------------------------------
// Baseline-PTX helpers (compute_103 virtual arch: no tcgen05/TMA-tensor)
// ---------------------------------------------------------------------------
__device__ __forceinline__ uint32_t smem_u32(const void* p) {
    uint32_t a;
    asm("{ .reg .u64 t; cvta.to.shared.u64 t, %1; cvt.u32.u64 %0, t; }"
        : "=r"(a) : "l"(p));
    return a;
}
__device__ __forceinline__ void cp16(uint32_t dst, const void* src) {
    asm volatile("cp.async.ca.shared.global [%0], [%1], 16;"
                 :: "r"(dst), "l"(src) : "memory");
}
#define CP_COMMIT() asm volatile("cp.async.commit_group;" ::: "memory")
#define CP_WAIT(n)  asm volatile("cp.async.wait_group %0;" :: "n"(n) : "memory")

__device__ __forceinline__ void ldsm4(uint32_t& r0, uint32_t& r1,
                                      uint32_t& r2, uint32_t& r3, uint32_t a) {
    asm volatile("ldmatrix.sync.aligned.m8n8.x4.shared.b16 {%0,%1,%2,%3}, [%4];"
                 : "=r"(r0), "=r"(r1), "=r"(r2), "=r"(r3) : "r"(a));
}
__device__ __forceinline__ void mma16816(float* c, const uint32_t* a,
                                         uint32_t b0, uint32_t b1) {
    asm volatile(
        "mma.sync.aligned.m16n8k16.row.col.f32.bf16.bf16.f32 "
        "{%0,%1,%2,%3}, {%4,%5,%6,%7}, {%8,%9}, {%0,%1,%2,%3};"
        : "+f"(c[0]), "+f"(c[1]), "+f"(c[2]), "+f"(c[3])
        : "r"(a[0]), "r"(a[1]), "r"(a[2]), "r"(a[3]), "r"(b0), "r"(b1));
}

// Split x into bf16 hi + lo, packed pairs. Memory order: [x0, x1] -> hi1:hi0
__device__ __forceinline__ void split_pack(float x0, float x1,
                                           uint32_t& hi, uint32_t& lo) {
    __nv_bfloat16 h0 = __float2bfloat16(x0), h1 = __float2bfloat16(x1);
    hi = ((uint32_t)__bfloat16_as_ushort(h1) << 16) | (uint32_t)__bfloat16_as_ushort(h0);
    float r0 = x0 - __bfloat162float(h0), r1 = x1 - __bfloat162float(h1);
    __nv_bfloat16 g0 = __float2bfloat16(r0), g1 = __float2bfloat16(r1);
    lo = ((uint32_t)__bfloat16_as_ushort(g1) << 16) | (uint32_t)__bfloat16_as_ushort(g0);
}

// ---------------------------------------------------------------------------
// fp32 -> bf16 hi/lo split (flat)
// ---------------------------------------------------------------------------
__global__ __launch_bounds__(256) void split_kernel(const float* __restrict__ s,
                                                    __nv_bfloat16* __restrict__ hi,
                                                    __nv_bfloat16* __restrict__ lo,
                                                    int n4) {
    int i = blockIdx.x * blockDim.x + threadIdx.x;
    if (i >= n4) return;
    float4 v = ((const float4*)s)[i];
    uint32_t h01, l01, h23, l23;
    split_pack(v.x, v.y, h01, l01);
    split_pack(v.z, v.w, h23, l23);
    ((uint2*)hi)[i] = make_uint2(h01, h23);
    ((uint2*)lo)[i] = make_uint2(l01, l23);
}

// ---------------------------------------------------------------------------
// Split-bf16 HMMA GEMM (unchanged from round 3 — validated)
// ---------------------------------------------------------------------------
#define ROWP 40
#define ARR_BYTES (128 * ROWP * 2)
#define STAGE_BYTES (4 * ARR_BYTES)
#define GT_SMEM_TOTAL (2 * STAGE_BYTES)

__global__ __launch_bounds__(256) void tc_gemm(const __nv_bfloat16* __restrict__ Ahi,
                                               const __nv_bfloat16* __restrict__ Alo,
                                               const __nv_bfloat16* __restrict__ Bhi,
                                               const __nv_bfloat16* __restrict__ Blo,
                                               float* __restrict__ C,
                                               int N, int K) {
    extern __shared__ char smem_raw[];
    const uint32_t sb = smem_u32(smem_raw);
    const int tid = threadIdx.x;
    const int lane = tid & 31;
    const int warp = tid >> 5;
    const int wm = warp & 3;
    const int wn = warp >> 2;
    const int rowBase = blockIdx.y * 128;
    const int colBase = blockIdx.x * 128;

    const __nv_bfloat16* srcs[4] = {
        Ahi + (size_t)rowBase * K, Alo + (size_t)rowBase * K,
        Bhi + (size_t)colBase * K, Blo + (size_t)colBase * K };

    float acc[2][8][4];
#pragma unroll
    for (int mt = 0; mt < 2; ++mt)
#pragma unroll
        for (int nt = 0; nt < 8; ++nt)
#pragma unroll
            for (int r = 0; r < 4; ++r) acc[mt][nt][r] = 0.f;

    const int nstages = K >> 5;

    auto load_stage = [&](int c, int st) {
        const int k0 = c << 5;
#pragma unroll
        for (int arr = 0; arr < 4; ++arr) {
            const __nv_bfloat16* s = srcs[arr];
            uint32_t dbase = sb + st * STAGE_BYTES + arr * ARR_BYTES;
#pragma unroll
            for (int p = 0; p < 2; ++p) {
                int f = tid + p * 256;
                int r = f >> 2, kc = f & 3;
                cp16(dbase + (uint32_t)(r * ROWP + kc * 8) * 2,
                     s + (size_t)r * K + k0 + kc * 8);
            }
        }
    };

    const int arow = wm * 32 + (lane & 15);
    const int acolH = (lane >> 4) * 8;
    const int browIn = (lane & 7) + ((lane & 16) >> 1);
    const int bcolH = ((lane >> 3) & 1) * 8;

    load_stage(0, 0);
    CP_COMMIT();

    for (int c = 0; c < nstages; ++c) {
        const int st = c & 1;
        if (c + 1 < nstages) {
            load_stage(c + 1, (c + 1) & 1);
            CP_COMMIT();
            CP_WAIT(1);
        } else {
            CP_WAIT(0);
        }
        __syncthreads();

        uint32_t aHi = sb + st * STAGE_BYTES;
        uint32_t aLo = aHi + ARR_BYTES;
        uint32_t bHi = aHi + 2 * ARR_BYTES;
        uint32_t bLo = aHi + 3 * ARR_BYTES;

#pragma unroll
        for (int ks = 0; ks < 2; ++ks) {
            uint32_t ah[2][4], al[2][4];
#pragma unroll
            for (int mt = 0; mt < 2; ++mt) {
                uint32_t off = (uint32_t)((arow + mt * 16) * ROWP + ks * 16 + acolH) * 2;
                ldsm4(ah[mt][0], ah[mt][1], ah[mt][2], ah[mt][3], aHi + off);
                ldsm4(al[mt][0], al[mt][1], al[mt][2], al[mt][3], aLo + off);
            }
            uint32_t bh[4][4], bl[4][4];
#pragma unroll
            for (int nt2 = 0; nt2 < 4; ++nt2) {
                int row = wn * 64 + nt2 * 16 + browIn;
                uint32_t off = (uint32_t)(row * ROWP + ks * 16 + bcolH) * 2;
                ldsm4(bh[nt2][0], bh[nt2][1], bh[nt2][2], bh[nt2][3], bHi + off);
                ldsm4(bl[nt2][0], bl[nt2][1], bl[nt2][2], bl[nt2][3], bLo + off);
            }
#pragma unroll
            for (int mt = 0; mt < 2; ++mt)
#pragma unroll
                for (int nt = 0; nt < 8; ++nt) {
                    int nt2 = nt >> 1, pb = (nt & 1) * 2;
                    mma16816(acc[mt][nt], ah[mt], bh[nt2][pb], bh[nt2][pb + 1]);
                    mma16816(acc[mt][nt], ah[mt], bl[nt2][pb], bl[nt2][pb + 1]);
                    mma16816(acc[mt][nt], al[mt], bh[nt2][pb], bh[nt2][pb + 1]);
                }
        }
        __syncthreads();
    }

#pragma unroll
    for (int mt = 0; mt < 2; ++mt) {
        int row0 = rowBase + wm * 32 + mt * 16 + (lane >> 2);
#pragma unroll
        for (int nt = 0; nt < 8; ++nt) {
            int col = colBase + wn * 64 + nt * 8 + (lane & 3) * 2;
            *(float2*)&C[(size_t)row0 * N + col] =
                make_float2(acc[mt][nt][0], acc[mt][nt][1]);
            *(float2*)&C[(size_t)(row0 + 8) * N + col] =
                make_float2(acc[mt][nt][2], acc[mt][nt][3]);
        }
    }
}

// ---------------------------------------------------------------------------
// Prep: qkv fp32 -> Q(scaled),K bf16 hi/lo in [b,h,s,64]
// ---------------------------------------------------------------------------
__global__ __launch_bounds__(256) void prep_qk(const float* __restrict__ qkv,
                                               __nv_bfloat16* __restrict__ qhi,
                                               __nv_bfloat16* __restrict__ qlo,
                                               __nv_bfloat16* __restrict__ khi,
                                               __nv_bfloat16* __restrict__ klo) {
    int i = blockIdx.x * 256 + threadIdx.x;           // [b, s, h, hd4] : 1M
    int hd4 = i & 15;
    int h = (i >> 4) & 15;
    int s = (i >> 8) & 2047;
    int b = i >> 19;
    size_t src = ((size_t)(b * SS + s) * 3) * DD + h * HDIM + hd4 * 4;
    float4 q = *(const float4*)&qkv[src];
    float4 k = *(const float4*)&qkv[src + DD];
    q.x *= 0.125f; q.y *= 0.125f; q.z *= 0.125f; q.w *= 0.125f;
    size_t dst = ((size_t)(b * HH + h) * SS + s) * HDIM + hd4 * 4;
    uint32_t h01, l01, h23, l23;
    split_pack(q.x, q.y, h01, l01); split_pack(q.z, q.w, h23, l23);
    *(uint2*)&qhi[dst] = make_uint2(h01, h23);
    *(uint2*)&qlo[dst] = make_uint2(l01, l23);
    split_pack(k.x, k.y, h01, l01); split_pack(k.z, k.w, h23, l23);
    *(uint2*)&khi[dst] = make_uint2(h01, h23);
    *(uint2*)&klo[dst] = make_uint2(l01, l23);
}

// ---------------------------------------------------------------------------
// Prep: V fp32 -> transposed bf16 hi/lo [b,h,64(d),2048(s)]
// ---------------------------------------------------------------------------
__global__ __launch_bounds__(256) void prep_v(const float* __restrict__ qkv,
                                              __nv_bfloat16* __restrict__ vthi,
                                              __nv_bfloat16* __restrict__ vtlo) {
    __shared__ float tile[64][65];
    const int tid = threadIdx.x;
    const int b = blockIdx.z, h = blockIdx.y, sblk = blockIdx.x;
#pragma unroll
    for (int t = 0; t < 4; ++t) {
        int j = tid + t * 256;          // [r(64)][c4(16)]
        int r = j >> 4, c4 = j & 15;
        float4 v = *(const float4*)&qkv[((size_t)(b * SS + sblk * 64 + r) * 3 + 2) * DD +
                                        h * HDIM + c4 * 4];
        tile[r][c4 * 4 + 0] = v.x; tile[r][c4 * 4 + 1] = v.y;
        tile[r][c4 * 4 + 2] = v.z; tile[r][c4 * 4 + 3] = v.w;
    }
    __syncthreads();
#pragma unroll
    for (int t = 0; t < 4; ++t) {
        int j = tid + t * 256;          // [d(64)][s4(16)]
        int d = j >> 4, s4 = j & 15;
        float x0 = tile[s4 * 4 + 0][d], x1 = tile[s4 * 4 + 1][d];
        float x2 = tile[s4 * 4 + 2][d], x3 = tile[s4 * 4 + 3][d];
        uint32_t h01, l01, h23, l23;
        split_pack(x0, x1, h01, l01); split_pack(x2, x3, h23, l23);
        size_t dst = ((size_t)(b * HH + h) * HDIM + d) * SS + sblk * 64 + s4 * 4;
        *(uint2*)&vthi[dst] = make_uint2(h01, h23);
        *(uint2*)&vtlo[dst] = make_uint2(l01, l23);
    }
}

// ---------------------------------------------------------------------------
// HMMA flash attention (split-bf16, fp32 accum, online softmax).
// CTA: 128 q rows x (b,h). 8 warps x 16 q rows. KV blocks of 64, double-buffered.
// Writes bf16 hi/lo output directly (feeds out-projection tc_gemm).
// ---------------------------------------------------------------------------
#define ROWQ 72
#define QARR (128 * ROWQ * 2)          // 18432
#define KVARR (64 * ROWQ * 2)          // 9216
#define KVSTAGE (4 * KVARR)            // 36864
#define ATTN_SMEM (2 * QARR + 2 * KVSTAGE)  // 110592

__global__ __launch_bounds__(256, 1) void attn_mma(
        const __nv_bfloat16* __restrict__ qhi, const __nv_bfloat16* __restrict__ qlo,
        const __nv_bfloat16* __restrict__ khi, const __nv_bfloat16* __restrict__ klo,
        const __nv_bfloat16* __restrict__ vthi, const __nv_bfloat16* __restrict__ vtlo,
        __nv_bfloat16* __restrict__ ahi, __nv_bfloat16* __restrict__ alo) {
    extern __shared__ char smem_raw[];
    const uint32_t sb = smem_u32(smem_raw);
    const int tid = threadIdx.x;
    const int lane = tid & 31;
    const int warp = tid >> 5;
    const int b = blockIdx.z, h = blockIdx.y;
    const int q0 = blockIdx.x * 128;
    const size_t bh = (size_t)(b * HH + h);

    const __nv_bfloat16* qhp = qhi + (bh * SS + q0) * HDIM;
    const __nv_bfloat16* qlp = qlo + (bh * SS + q0) * HDIM;
    const __nv_bfloat16* khp = khi + bh * SS * HDIM;
    const __nv_bfloat16* klp = klo + bh * SS * HDIM;
    const __nv_bfloat16* vhp = vthi + bh * HDIM * SS;
    const __nv_bfloat16* vlp = vtlo + bh * HDIM * SS;

    // Q tiles -> smem (group 0, together with KV block 0)
#pragma unroll
    for (int p = 0; p < 4; ++p) {
        int f = tid + p * 256;         // [r(128)][cq(8)]
        int r = f >> 3, cq = f & 7;
        uint32_t off = (uint32_t)(r * ROWQ + cq * 8) * 2;
        cp16(sb + off, qhp + (size_t)r * HDIM + cq * 8);
        cp16(sb + QARR + off, qlp + (size_t)r * HDIM + cq * 8);
    }

    auto load_kv = [&](int blk, int st) {
        const int kv0 = blk * 64;
        uint32_t base = sb + 2 * QARR + st * KVSTAGE;
#pragma unroll
        for (int p = 0; p < 2; ++p) {
            int f = tid + p * 256;     // [r(64)][cq(8)]
            int r = f >> 3, cq = f & 7;
            uint32_t off = (uint32_t)(r * ROWQ + cq * 8) * 2;
            size_t koff = (size_t)(kv0 + r) * HDIM + cq * 8;
            size_t voff = (size_t)r * SS + kv0 + cq * 8;
            cp16(base + off, khp + koff);
            cp16(base + KVARR + off, klp + koff);
            cp16(base + 2 * KVARR + off, vhp + voff);
            cp16(base + 3 * KVARR + off, vlp + voff);
        }
    };

    load_kv(0, 0);
    CP_COMMIT();

    const int arow = warp * 16 + (lane & 15);
    const int acolH = (lane >> 4) * 8;
    const int browIn = (lane & 7) + ((lane & 16) >> 1);
    const int bcolH = ((lane >> 3) & 1) * 8;

    float m0 = -1e30f, m1 = -1e30f, l0 = 0.f, l1 = 0.f;
    float oacc[8][4];
#pragma unroll
    for (int nt = 0; nt < 8; ++nt)
#pragma unroll
        for (int r = 0; r < 4; ++r) oacc[nt][r] = 0.f;

    for (int blk = 0; blk < SS / 64; ++blk) {
        const int st = blk & 1;
        if (blk + 1 < SS / 64) {
            load_kv(blk + 1, st ^ 1);
            CP_COMMIT();
            CP_WAIT(1);
        } else {
            CP_WAIT(0);
        }
        __syncthreads();

        const uint32_t kb = sb + 2 * QARR + st * KVSTAGE;
        const uint32_t vb = kb + 2 * KVARR;

        // ---- S = Q K^T (3-term split), fp32 accum ----
        float sacc[8][4];
#pragma unroll
        for (int nt = 0; nt < 8; ++nt)
#pragma unroll
            for (int r = 0; r < 4; ++r) sacc[nt][r] = 0.f;

#pragma unroll
        for (int ks = 0; ks < 4; ++ks) {
            uint32_t qh[4], ql[4];
            uint32_t aoff = (uint32_t)(arow * ROWQ + ks * 16 + acolH) * 2;
            ldsm4(qh[0], qh[1], qh[2], qh[3], sb + aoff);
            ldsm4(ql[0], ql[1], ql[2], ql[3], sb + QARR + aoff);
            uint32_t bh[4][4], bl[4][4];
#pragma unroll
            for (int n2 = 0; n2 < 4; ++n2) {
                uint32_t boff = (uint32_t)((n2 * 16 + browIn) * ROWQ + ks * 16 + bcolH) * 2;
                ldsm4(bh[n2][0], bh[n2][1], bh[n2][2], bh[n2][3], kb + boff);
                ldsm4(bl[n2][0], bl[n2][1], bl[n2][2], bl[n2][3], kb + KVARR + boff);
            }
#pragma unroll
            for (int nt = 0; nt < 8; ++nt) {
                int n2 = nt >> 1, pb = (nt & 1) * 2;
                mma16816(sacc[nt], qh, bh[n2][pb], bh[n2][pb + 1]);
                mma16816(sacc[nt], qh, bl[n2][pb], bl[n2][pb + 1]);
                mma16816(sacc[nt], ql, bh[n2][pb], bh[n2][pb + 1]);
            }
        }

        // ---- online softmax (rows r0 = lane>>2 and r0+8) ----
        float mx0 = -1e30f, mx1 = -1e30f;
#pragma unroll
        for (int nt = 0; nt < 8; ++nt) {
            mx0 = fmaxf(mx0, fmaxf(sacc[nt][0], sacc[nt][1]));
            mx1 = fmaxf(mx1, fmaxf(sacc[nt][2], sacc[nt][3]));
        }
        mx0 = fmaxf(mx0, __shfl_xor_sync(0xffffffffu, mx0, 1));
        mx0 = fmaxf(mx0, __shfl_xor_sync(0xffffffffu, mx0, 2));
        mx1 = fmaxf(mx1, __shfl_xor_sync(0xffffffffu, mx1, 1));
        mx1 = fmaxf(mx1, __shfl_xor_sync(0xffffffffu, mx1, 2));
        float mn0 = fmaxf(m0, mx0), mn1 = fmaxf(m1, mx1);
        float al0 = __expf(m0 - mn0), al1 = __expf(m1 - mn1);
        m0 = mn0; m1 = mn1;
        float sum0 = 0.f, sum1 = 0.f;
#pragma unroll
        for (int nt = 0; nt < 8; ++nt) {
            sacc[nt][0] = __expf(sacc[nt][0] - m0);
            sacc[nt][1] = __expf(sacc[nt][1] - m0);
            sacc[nt][2] = __expf(sacc[nt][2] - m1);
            sacc[nt][3] = __expf(sacc[nt][3] - m1);
            sum0 += sacc[nt][0] + sacc[nt][1];
            sum1 += sacc[nt][2] + sacc[nt][3];
        }
        sum0 += __shfl_xor_sync(0xffffffffu, sum0, 1);
        sum0 += __shfl_xor_sync(0xffffffffu, sum0, 2);
        sum1 += __shfl_xor_sync(0xffffffffu, sum1, 1);
        sum1 += __shfl_xor_sync(0xffffffffu, sum1, 2);
        l0 = l0 * al0 + sum0;
        l1 = l1 * al1 + sum1;
#pragma unroll
        for (int nt = 0; nt < 8; ++nt) {
            oacc[nt][0] *= al0; oacc[nt][1] *= al0;
            oacc[nt][2] *= al1; oacc[nt][3] *= al1;
        }

        // ---- P -> bf16 hi/lo A-fragments ----
        uint32_t ph[4][4], pl[4][4];
#pragma unroll
        for (int t = 0; t < 4; ++t) {
            split_pack(sacc[2 * t][0],     sacc[2 * t][1],     ph[t][0], pl[t][0]);
            split_pack(sacc[2 * t][2],     sacc[2 * t][3],     ph[t][1], pl[t][1]);
            split_pack(sacc[2 * t + 1][0], sacc[2 * t + 1][1], ph[t][2], pl[t][2]);
            split_pack(sacc[2 * t + 1][2], sacc[2 * t + 1][3], ph[t][3], pl[t][3]);
        }

        // ---- O += P V (3-term split) ----
#pragma unroll
        for (int t = 0; t < 4; ++t) {
            uint32_t vh[4][4], vl[4][4];
#pragma unroll
            for (int n2 = 0; n2 < 4; ++n2) {
                uint32_t boff = (uint32_t)((n2 * 16 + browIn) * ROWQ + t * 16 + bcolH) * 2;
                ldsm4(vh[n2][0], vh[n2][1], vh[n2][2], vh[n2][3], vb + boff);
                ldsm4(vl[n2][0], vl[n2][1], vl[n2][2], vl[n2][3], vb + KVARR + boff);
            }
#pragma unroll
            for (int nt = 0; nt < 8; ++nt) {
                int n2 = nt >> 1, pb = (nt & 1) * 2;
                mma16816(oacc[nt], ph[t], vh[n2][pb], vh[n2][pb + 1]);
                mma16816(oacc[nt], ph[t], vl[n2][pb], vl[n2][pb + 1]);
                mma16816(oacc[nt], pl[t], vh[n2][pb], vh[n2][pb + 1]);
            }
        }
        __syncthreads();
    }

    // ---- epilogue: normalize and write bf16 hi/lo ----
    const float inv0 = 1.0f / l0, inv1 = 1.0f / l1;
    const int row0 = q0 + warp * 16 + (lane >> 2);
#pragma unroll
    for (int nt = 0; nt < 8; ++nt) {
        int col = h * HDIM + nt * 8 + (lane & 3) * 2;
        uint32_t hp, lp;
        split_pack(oacc[nt][0] * inv0, oacc[nt][1] * inv0, hp, lp);
        size_t idx0 = (size_t)(b * SS + row0) * DD + col;
        *(uint32_t*)&ahi[idx0] = hp;
        *(uint32_t*)&alo[idx0] = lp;
        split_pack(oacc[nt][2] * inv1, oacc[nt][3] * inv1, hp, lp);
        size_t idx1 = (size_t)(b * SS + row0 + 8) * DD + col;
        *(uint32_t*)&ahi[idx1] = hp;
        *(uint32_t*)&alo[idx1] = lp;
    }
}

// ---------------------------------------------------------------------------
// Launch
// ---------------------------------------------------------------------------
extern "C" void kernel_launch(void* const* d_in, const int* in_sizes, int n_in,
                              void* d_out, int out_size) {
    const float* x     = (const float*)d_in[0];
    const float* w_qkv = (const float*)d_in[1];
    const float* w_out = (const float*)d_in[2];
    float* out = (float*)d_out;

    void* p;
    cudaGetSymbolAddress(&p, g_qkv);  float* qkv = (float*)p;
    __nv_bfloat16 *xhi, *xlo, *whi, *wlo, *ohi, *olo, *ahi, *alo;
    __nv_bfloat16 *qhi, *qlo, *khi, *klo, *vthi, *vtlo;
    cudaGetSymbolAddress(&p, g_xhi); xhi = (__nv_bfloat16*)p;
    cudaGetSymbolAddress(&p, g_xlo); xlo = (__nv_bfloat16*)p;
    cudaGetSymbolAddress(&p, g_whi); whi = (__nv_bfloat16*)p;
    cudaGetSymbolAddress(&p, g_wlo); wlo = (__nv_bfloat16*)p;
    cudaGetSymbolAddress(&p, g_ohi); ohi = (__nv_bfloat16*)p;
    cudaGetSymbolAddress(&p, g_olo); olo = (__nv_bfloat16*)p;
    cudaGetSymbolAddress(&p, g_ahi); ahi = (__nv_bfloat16*)p;
    cudaGetSymbolAddress(&p, g_alo); alo = (__nv_bfloat16*)p;
    cudaGetSymbolAddress(&p, g_qhi); qhi = (__nv_bfloat16*)p;
    cudaGetSymbolAddress(&p, g_qlo); qlo = (__nv_bfloat16*)p;
    cudaGetSymbolAddress(&p, g_khi); khi = (__nv_bfloat16*)p;
    cudaGetSymbolAddress(&p, g_klo); klo = (__nv_bfloat16*)p;
    cudaGetSymbolAddress(&p, g_vthi); vthi = (__nv_bfloat16*)p;
    cudaGetSymbolAddress(&p, g_vtlo); vtlo = (__nv_bfloat16*)p;

    cudaFuncSetAttribute(tc_gemm, cudaFuncAttributeMaxDynamicSharedMemorySize,
                         GT_SMEM_TOTAL);
    cudaFuncSetAttribute(attn_mma, cudaFuncAttributeMaxDynamicSharedMemorySize,
                         ATTN_SMEM);

    // 0) splits
    {
        int n4x = (BB * SS * DD) / 4;
        split_kernel<<<(n4x + 255) / 256, 256>>>(x, xhi, xlo, n4x);
        int n4w = (3 * DD * DD) / 4;
        split_kernel<<<(n4w + 255) / 256, 256>>>(w_qkv, whi, wlo, n4w);
        int n4o = (DD * DD) / 4;
        split_kernel<<<(n4o + 255) / 256, 256>>>(w_out, ohi, olo, n4o);
    }

    // 1) QKV projection
    {
        dim3 grid(3 * DD / 128, (BB * SS) / 128);
        tc_gemm<<<grid, 256, GT_SMEM_TOTAL>>>(xhi, xlo, whi, wlo, qkv, 3 * DD, KDIM);
    }

    // 2) attention preprocessing
    prep_qk<<<4096, 256>>>(qkv, qhi, qlo, khi, klo);
    {
        dim3 grid(SS / 64, HH, BB);
        prep_v<<<grid, 256>>>(qkv, vthi, vtlo);
    }

    // 3) HMMA flash attention (writes ahi/alo)
    {
        dim3 grid(SS / 128, HH, BB);
        attn_mma<<<grid, 256, ATTN_SMEM>>>(qhi, qlo, khi, klo, vthi, vtlo, ahi, alo);
    }

    // 4) output projection
    {
        dim3 grid(DD / 128, (BB * SS) / 128);
        tc_gemm<<<grid, 256, GT_SMEM_TOTAL>>>(ahi, alo, ohi, olo, out, DD, KDIM);
    }
}

// round 5
// speedup vs baseline: 3.6340x; 1.0453x over previous
#include <cuda_runtime.h>
#include <cuda_bf16.h>
#include <cstdint>
#include <cstddef>

// Problem constants
#define BB 2
#define SS 2048
#define DD 1024
#define HH 16
#define HDIM 64
#define KDIM 1024

// Scratch (no cudaMalloc allowed)
__device__ float g_qkv[BB * SS * 3 * DD];
__device__ __nv_bfloat16 g_xhi[BB * SS * DD],  g_xlo[BB * SS * DD];
__device__ __nv_bfloat16 g_whi[3 * DD * DD],   g_wlo[3 * DD * DD];
__device__ __nv_bfloat16 g_ohi[DD * DD],       g_olo[DD * DD];
__device__ __nv_bfloat16 g_ahi[BB * SS * DD],  g_alo[BB * SS * DD];
__device__ __nv_bfloat16 g_qhi[BB * HH * SS * HDIM], g_qlo[BB * HH * SS * HDIM];
__device__ __nv_bfloat16 g_khi[BB * HH * SS * HDIM], g_klo[BB * HH * SS * HDIM];
__device__ __nv_bfloat16 g_vthi[BB * HH * HDIM * SS], g_vtlo[BB * HH * HDIM * SS];

// ---------------------------------------------------------------------------
// Baseline-PTX helpers
// ---------------------------------------------------------------------------
__device__ __forceinline__ uint32_t smem_u32(const void* p) {
    uint32_t a;
    asm("{ .reg .u64 t; cvta.to.shared.u64 t, %1; cvt.u32.u64 %0, t; }"
        : "=r"(a) : "l"(p));
    return a;
}
__device__ __forceinline__ void cp16(uint32_t dst, const void* src) {
    asm volatile("cp.async.ca.shared.global [%0], [%1], 16;"
                 :: "r"(dst), "l"(src) : "memory");
}
#define CP_COMMIT() asm volatile("cp.async.commit_group;" ::: "memory")
#define CP_WAIT(n)  asm volatile("cp.async.wait_group %0;" :: "n"(n) : "memory")

__device__ __forceinline__ void ldsm4(uint32_t& r0, uint32_t& r1,
                                      uint32_t& r2, uint32_t& r3, uint32_t a) {
    asm volatile("ldmatrix.sync.aligned.m8n8.x4.shared.b16 {%0,%1,%2,%3}, [%4];"
                 : "=r"(r0), "=r"(r1), "=r"(r2), "=r"(r3) : "r"(a));
}
__device__ __forceinline__ void mma16816(float* c, const uint32_t* a,
                                         uint32_t b0, uint32_t b1) {
    asm volatile(
        "mma.sync.aligned.m16n8k16.row.col.f32.bf16.bf16.f32 "
        "{%0,%1,%2,%3}, {%4,%5,%6,%7}, {%8,%9}, {%0,%1,%2,%3};"
        : "+f"(c[0]), "+f"(c[1]), "+f"(c[2]), "+f"(c[3])
        : "r"(a[0]), "r"(a[1]), "r"(a[2]), "r"(a[3]), "r"(b0), "r"(b1));
}
__device__ __forceinline__ void split_pack(float x0, float x1,
                                           uint32_t& hi, uint32_t& lo) {
    __nv_bfloat16 h0 = __float2bfloat16(x0), h1 = __float2bfloat16(x1);
    hi = ((uint32_t)__bfloat16_as_ushort(h1) << 16) | (uint32_t)__bfloat16_as_ushort(h0);
    float r0 = x0 - __bfloat162float(h0), r1 = x1 - __bfloat162float(h1);
    __nv_bfloat16 g0 = __float2bfloat16(r0), g1 = __float2bfloat16(r1);
    lo = ((uint32_t)__bfloat16_as_ushort(g1) << 16) | (uint32_t)__bfloat16_as_ushort(g0);
}

// ---------------------------------------------------------------------------
// fp32 -> bf16 hi/lo split (flat)
// ---------------------------------------------------------------------------
__global__ __launch_bounds__(256) void split_kernel(const float* __restrict__ s,
                                                    __nv_bfloat16* __restrict__ hi,
                                                    __nv_bfloat16* __restrict__ lo,
                                                    int n4) {
    int i = blockIdx.x * blockDim.x + threadIdx.x;
    if (i >= n4) return;
    float4 v = ((const float4*)s)[i];
    uint32_t h01, l01, h23, l23;
    split_pack(v.x, v.y, h01, l01);
    split_pack(v.z, v.w, h23, l23);
    ((uint2*)hi)[i] = make_uint2(h01, h23);
    ((uint2*)lo)[i] = make_uint2(l01, l23);
}

// ---------------------------------------------------------------------------
// Split-bf16 HMMA GEMM v2: CTA 128x128, 4 warps (2x2), warp tile 64x64.
// Term-outermost MMA order (acc RAW distance 32). 128 threads, 2 CTAs/SM.
// ---------------------------------------------------------------------------
#define ROWP 40
#define ARR_BYTES (128 * ROWP * 2)
#define STAGE_BYTES (4 * ARR_BYTES)
#define GT_SMEM_TOTAL (2 * STAGE_BYTES)

__global__ __launch_bounds__(128) void tc_gemm(const __nv_bfloat16* __restrict__ Ahi,
                                               const __nv_bfloat16* __restrict__ Alo,
                                               const __nv_bfloat16* __restrict__ Bhi,
                                               const __nv_bfloat16* __restrict__ Blo,
                                               float* __restrict__ C,
                                               int N, int K) {
    extern __shared__ char smem_raw[];
    const uint32_t sb = smem_u32(smem_raw);
    const int tid = threadIdx.x;
    const int lane = tid & 31;
    const int warp = tid >> 5;
    const int wm = warp & 1;          // rows wm*64
    const int wn = warp >> 1;         // cols wn*64
    const int rowBase = blockIdx.y * 128;
    const int colBase = blockIdx.x * 128;

    const __nv_bfloat16* srcs[4] = {
        Ahi + (size_t)rowBase * K, Alo + (size_t)rowBase * K,
        Bhi + (size_t)colBase * K, Blo + (size_t)colBase * K };

    float acc[4][8][4];
#pragma unroll
    for (int mt = 0; mt < 4; ++mt)
#pragma unroll
        for (int nt = 0; nt < 8; ++nt)
#pragma unroll
            for (int r = 0; r < 4; ++r) acc[mt][nt][r] = 0.f;

    const int nstages = K >> 5;

    auto load_stage = [&](int c, int st) {
        const int k0 = c << 5;
#pragma unroll
        for (int arr = 0; arr < 4; ++arr) {
            const __nv_bfloat16* s = srcs[arr];
            uint32_t dbase = sb + st * STAGE_BYTES + arr * ARR_BYTES;
#pragma unroll
            for (int p = 0; p < 4; ++p) {
                int f = tid + p * 128;
                int r = f >> 2, kc = f & 3;
                cp16(dbase + (uint32_t)(r * ROWP + kc * 8) * 2,
                     s + (size_t)r * K + k0 + kc * 8);
            }
        }
    };

    const int arowIn = (lane & 15);
    const int acolH = (lane >> 4) * 8;
    const int browIn = (lane & 7) + ((lane & 16) >> 1);
    const int bcolH = ((lane >> 3) & 1) * 8;

    load_stage(0, 0);
    CP_COMMIT();

    for (int c = 0; c < nstages; ++c) {
        const int st = c & 1;
        if (c + 1 < nstages) {
            load_stage(c + 1, (c + 1) & 1);
            CP_COMMIT();
            CP_WAIT(1);
        } else {
            CP_WAIT(0);
        }
        __syncthreads();

        uint32_t aHi = sb + st * STAGE_BYTES;
        uint32_t aLo = aHi + ARR_BYTES;
        uint32_t bHi = aHi + 2 * ARR_BYTES;
        uint32_t bLo = aHi + 3 * ARR_BYTES;

#pragma unroll
        for (int ks = 0; ks < 2; ++ks) {
            uint32_t ah[4][4], al[4][4];
#pragma unroll
            for (int mt = 0; mt < 4; ++mt) {
                uint32_t off = (uint32_t)((wm * 64 + mt * 16 + arowIn) * ROWP +
                                          ks * 16 + acolH) * 2;
                ldsm4(ah[mt][0], ah[mt][1], ah[mt][2], ah[mt][3], aHi + off);
                ldsm4(al[mt][0], al[mt][1], al[mt][2], al[mt][3], aLo + off);
            }
            uint32_t bh[4][4], bl[4][4];
#pragma unroll
            for (int n2 = 0; n2 < 4; ++n2) {
                uint32_t off = (uint32_t)((wn * 64 + n2 * 16 + browIn) * ROWP +
                                          ks * 16 + bcolH) * 2;
                ldsm4(bh[n2][0], bh[n2][1], bh[n2][2], bh[n2][3], bHi + off);
                ldsm4(bl[n2][0], bl[n2][1], bl[n2][2], bl[n2][3], bLo + off);
            }
            // term-outermost: same acc revisited only every 32 MMAs
#pragma unroll
            for (int mt = 0; mt < 4; ++mt)
#pragma unroll
                for (int nt = 0; nt < 8; ++nt) {
                    int n2 = nt >> 1, pb = (nt & 1) * 2;
                    mma16816(acc[mt][nt], ah[mt], bh[n2][pb], bh[n2][pb + 1]);
                }
#pragma unroll
            for (int mt = 0; mt < 4; ++mt)
#pragma unroll
                for (int nt = 0; nt < 8; ++nt) {
                    int n2 = nt >> 1, pb = (nt & 1) * 2;
                    mma16816(acc[mt][nt], ah[mt], bl[n2][pb], bl[n2][pb + 1]);
                }
#pragma unroll
            for (int mt = 0; mt < 4; ++mt)
#pragma unroll
                for (int nt = 0; nt < 8; ++nt) {
                    int n2 = nt >> 1, pb = (nt & 1) * 2;
                    mma16816(acc[mt][nt], al[mt], bh[n2][pb], bh[n2][pb + 1]);
                }
        }
        __syncthreads();
    }

#pragma unroll
    for (int mt = 0; mt < 4; ++mt) {
        int row0 = rowBase + wm * 64 + mt * 16 + (lane >> 2);
#pragma unroll
        for (int nt = 0; nt < 8; ++nt) {
            int col = colBase + wn * 64 + nt * 8 + (lane & 3) * 2;
            *(float2*)&C[(size_t)row0 * N + col] =
                make_float2(acc[mt][nt][0], acc[mt][nt][1]);
            *(float2*)&C[(size_t)(row0 + 8) * N + col] =
                make_float2(acc[mt][nt][2], acc[mt][nt][3]);
        }
    }
}

// ---------------------------------------------------------------------------
// Prep kernels (unchanged)
// ---------------------------------------------------------------------------
__global__ __launch_bounds__(256) void prep_qk(const float* __restrict__ qkv,
                                               __nv_bfloat16* __restrict__ qhi,
                                               __nv_bfloat16* __restrict__ qlo,
                                               __nv_bfloat16* __restrict__ khi,
                                               __nv_bfloat16* __restrict__ klo) {
    int i = blockIdx.x * 256 + threadIdx.x;
    int hd4 = i & 15;
    int h = (i >> 4) & 15;
    int s = (i >> 8) & 2047;
    int b = i >> 19;
    size_t src = ((size_t)(b * SS + s) * 3) * DD + h * HDIM + hd4 * 4;
    float4 q = *(const float4*)&qkv[src];
    float4 k = *(const float4*)&qkv[src + DD];
    q.x *= 0.125f; q.y *= 0.125f; q.z *= 0.125f; q.w *= 0.125f;
    size_t dst = ((size_t)(b * HH + h) * SS + s) * HDIM + hd4 * 4;
    uint32_t h01, l01, h23, l23;
    split_pack(q.x, q.y, h01, l01); split_pack(q.z, q.w, h23, l23);
    *(uint2*)&qhi[dst] = make_uint2(h01, h23);
    *(uint2*)&qlo[dst] = make_uint2(l01, l23);
    split_pack(k.x, k.y, h01, l01); split_pack(k.z, k.w, h23, l23);
    *(uint2*)&khi[dst] = make_uint2(h01, h23);
    *(uint2*)&klo[dst] = make_uint2(l01, l23);
}

__global__ __launch_bounds__(256) void prep_v(const float* __restrict__ qkv,
                                              __nv_bfloat16* __restrict__ vthi,
                                              __nv_bfloat16* __restrict__ vtlo) {
    __shared__ float tile[64][65];
    const int tid = threadIdx.x;
    const int b = blockIdx.z, h = blockIdx.y, sblk = blockIdx.x;
#pragma unroll
    for (int t = 0; t < 4; ++t) {
        int j = tid + t * 256;
        int r = j >> 4, c4 = j & 15;
        float4 v = *(const float4*)&qkv[((size_t)(b * SS + sblk * 64 + r) * 3 + 2) * DD +
                                        h * HDIM + c4 * 4];
        tile[r][c4 * 4 + 0] = v.x; tile[r][c4 * 4 + 1] = v.y;
        tile[r][c4 * 4 + 2] = v.z; tile[r][c4 * 4 + 3] = v.w;
    }
    __syncthreads();
#pragma unroll
    for (int t = 0; t < 4; ++t) {
        int j = tid + t * 256;
        int d = j >> 4, s4 = j & 15;
        float x0 = tile[s4 * 4 + 0][d], x1 = tile[s4 * 4 + 1][d];
        float x2 = tile[s4 * 4 + 2][d], x3 = tile[s4 * 4 + 3][d];
        uint32_t h01, l01, h23, l23;
        split_pack(x0, x1, h01, l01); split_pack(x2, x3, h23, l23);
        size_t dst = ((size_t)(b * HH + h) * HDIM + d) * SS + sblk * 64 + s4 * 4;
        *(uint2*)&vthi[dst] = make_uint2(h01, h23);
        *(uint2*)&vtlo[dst] = make_uint2(l01, l23);
    }
}

// ---------------------------------------------------------------------------
// HMMA flash attention v2: BQ=256, 8 warps, warp tile 32x64 (mt=2).
// ---------------------------------------------------------------------------
#define BQA 256
#define ROWQ 72
#define QARR (BQA * ROWQ * 2)               // 36864
#define KVARR (64 * ROWQ * 2)               // 9216
#define KVSTAGE (4 * KVARR)                 // 36864
#define ATTN_SMEM (2 * QARR + 2 * KVSTAGE)  // 147456

__global__ __launch_bounds__(256, 1) void attn_mma(
        const __nv_bfloat16* __restrict__ qhi, const __nv_bfloat16* __restrict__ qlo,
        const __nv_bfloat16* __restrict__ khi, const __nv_bfloat16* __restrict__ klo,
        const __nv_bfloat16* __restrict__ vthi, const __nv_bfloat16* __restrict__ vtlo,
        __nv_bfloat16* __restrict__ ahi, __nv_bfloat16* __restrict__ alo) {
    extern __shared__ char smem_raw[];
    const uint32_t sb = smem_u32(smem_raw);
    const int tid = threadIdx.x;
    const int lane = tid & 31;
    const int warp = tid >> 5;
    const int b = blockIdx.z, h = blockIdx.y;
    const int q0 = blockIdx.x * BQA;
    const size_t bh = (size_t)(b * HH + h);

    const __nv_bfloat16* qhp = qhi + (bh * SS + q0) * HDIM;
    const __nv_bfloat16* qlp = qlo + (bh * SS + q0) * HDIM;
    const __nv_bfloat16* khp = khi + bh * SS * HDIM;
    const __nv_bfloat16* klp = klo + bh * SS * HDIM;
    const __nv_bfloat16* vhp = vthi + bh * HDIM * SS;
    const __nv_bfloat16* vlp = vtlo + bh * HDIM * SS;

    // Q tiles -> smem (group 0 with KV block 0)
#pragma unroll
    for (int p = 0; p < 8; ++p) {
        int f = tid + p * 256;         // 0..2047
        int r = f >> 3, cq = f & 7;
        uint32_t off = (uint32_t)(r * ROWQ + cq * 8) * 2;
        cp16(sb + off, qhp + (size_t)r * HDIM + cq * 8);
        cp16(sb + QARR + off, qlp + (size_t)r * HDIM + cq * 8);
    }

    auto load_kv = [&](int blk, int st) {
        const int kv0 = blk * 64;
        uint32_t base = sb + 2 * QARR + st * KVSTAGE;
#pragma unroll
        for (int p = 0; p < 2; ++p) {
            int f = tid + p * 256;
            int r = f >> 3, cq = f & 7;
            uint32_t off = (uint32_t)(r * ROWQ + cq * 8) * 2;
            size_t koff = (size_t)(kv0 + r) * HDIM + cq * 8;
            size_t voff = (size_t)r * SS + kv0 + cq * 8;
            cp16(base + off, khp + koff);
            cp16(base + KVARR + off, klp + koff);
            cp16(base + 2 * KVARR + off, vhp + voff);
            cp16(base + 3 * KVARR + off, vlp + voff);
        }
    };

    load_kv(0, 0);
    CP_COMMIT();

    const int arowIn = (lane & 15);
    const int acolH = (lane >> 4) * 8;
    const int browIn = (lane & 7) + ((lane & 16) >> 1);
    const int bcolH = ((lane >> 3) & 1) * 8;

    float mrow[2][2], lrow[2][2];
    float oacc[2][8][4];
#pragma unroll
    for (int mt = 0; mt < 2; ++mt) {
        mrow[mt][0] = -1e30f; mrow[mt][1] = -1e30f;
        lrow[mt][0] = 0.f;    lrow[mt][1] = 0.f;
#pragma unroll
        for (int nt = 0; nt < 8; ++nt)
#pragma unroll
            for (int r = 0; r < 4; ++r) oacc[mt][nt][r] = 0.f;
    }

    for (int blk = 0; blk < SS / 64; ++blk) {
        const int st = blk & 1;
        if (blk + 1 < SS / 64) {
            load_kv(blk + 1, st ^ 1);
            CP_COMMIT();
            CP_WAIT(1);
        } else {
            CP_WAIT(0);
        }
        __syncthreads();

        const uint32_t kb = sb + 2 * QARR + st * KVSTAGE;
        const uint32_t vb = kb + 2 * KVARR;

        // ---- S = Q K^T ----
        float sacc[2][8][4];
#pragma unroll
        for (int mt = 0; mt < 2; ++mt)
#pragma unroll
            for (int nt = 0; nt < 8; ++nt)
#pragma unroll
                for (int r = 0; r < 4; ++r) sacc[mt][nt][r] = 0.f;

#pragma unroll
        for (int ks = 0; ks < 4; ++ks) {
            uint32_t qh[2][4], ql[2][4];
#pragma unroll
            for (int mt = 0; mt < 2; ++mt) {
                uint32_t aoff = (uint32_t)((warp * 32 + mt * 16 + arowIn) * ROWQ +
                                           ks * 16 + acolH) * 2;
                ldsm4(qh[mt][0], qh[mt][1], qh[mt][2], qh[mt][3], sb + aoff);
                ldsm4(ql[mt][0], ql[mt][1], ql[mt][2], ql[mt][3], sb + QARR + aoff);
            }
            uint32_t kh[4][4], kl[4][4];
#pragma unroll
            for (int n2 = 0; n2 < 4; ++n2) {
                uint32_t boff = (uint32_t)((n2 * 16 + browIn) * ROWQ + ks * 16 + bcolH) * 2;
                ldsm4(kh[n2][0], kh[n2][1], kh[n2][2], kh[n2][3], kb + boff);
                ldsm4(kl[n2][0], kl[n2][1], kl[n2][2], kl[n2][3], kb + KVARR + boff);
            }
#pragma unroll
            for (int mt = 0; mt < 2; ++mt)
#pragma unroll
                for (int nt = 0; nt < 8; ++nt) {
                    int n2 = nt >> 1, pb = (nt & 1) * 2;
                    mma16816(sacc[mt][nt], qh[mt], kh[n2][pb], kh[n2][pb + 1]);
                }
#pragma unroll
            for (int mt = 0; mt < 2; ++mt)
#pragma unroll
                for (int nt = 0; nt < 8; ++nt) {
                    int n2 = nt >> 1, pb = (nt & 1) * 2;
                    mma16816(sacc[mt][nt], qh[mt], kl[n2][pb], kl[n2][pb + 1]);
                }
#pragma unroll
            for (int mt = 0; mt < 2; ++mt)
#pragma unroll
                for (int nt = 0; nt < 8; ++nt) {
                    int n2 = nt >> 1, pb = (nt & 1) * 2;
                    mma16816(sacc[mt][nt], ql[mt], kh[n2][pb], kh[n2][pb + 1]);
                }
        }

        // ---- online softmax per mt ----
#pragma unroll
        for (int mt = 0; mt < 2; ++mt) {
            float mx0 = -1e30f, mx1 = -1e30f;
#pragma unroll
            for (int nt = 0; nt < 8; ++nt) {
                mx0 = fmaxf(mx0, fmaxf(sacc[mt][nt][0], sacc[mt][nt][1]));
                mx1 = fmaxf(mx1, fmaxf(sacc[mt][nt][2], sacc[mt][nt][3]));
            }
            mx0 = fmaxf(mx0, __shfl_xor_sync(0xffffffffu, mx0, 1));
            mx0 = fmaxf(mx0, __shfl_xor_sync(0xffffffffu, mx0, 2));
            mx1 = fmaxf(mx1, __shfl_xor_sync(0xffffffffu, mx1, 1));
            mx1 = fmaxf(mx1, __shfl_xor_sync(0xffffffffu, mx1, 2));
            float mn0 = fmaxf(mrow[mt][0], mx0), mn1 = fmaxf(mrow[mt][1], mx1);
            float al0 = __expf(mrow[mt][0] - mn0), al1 = __expf(mrow[mt][1] - mn1);
            mrow[mt][0] = mn0; mrow[mt][1] = mn1;
            float sum0 = 0.f, sum1 = 0.f;
#pragma unroll
            for (int nt = 0; nt < 8; ++nt) {
                sacc[mt][nt][0] = __expf(sacc[mt][nt][0] - mn0);
                sacc[mt][nt][1] = __expf(sacc[mt][nt][1] - mn0);
                sacc[mt][nt][2] = __expf(sacc[mt][nt][2] - mn1);
                sacc[mt][nt][3] = __expf(sacc[mt][nt][3] - mn1);
                sum0 += sacc[mt][nt][0] + sacc[mt][nt][1];
                sum1 += sacc[mt][nt][2] + sacc[mt][nt][3];
            }
            sum0 += __shfl_xor_sync(0xffffffffu, sum0, 1);
            sum0 += __shfl_xor_sync(0xffffffffu, sum0, 2);
            sum1 += __shfl_xor_sync(0xffffffffu, sum1, 1);
            sum1 += __shfl_xor_sync(0xffffffffu, sum1, 2);
            lrow[mt][0] = lrow[mt][0] * al0 + sum0;
            lrow[mt][1] = lrow[mt][1] * al1 + sum1;
#pragma unroll
            for (int nt = 0; nt < 8; ++nt) {
                oacc[mt][nt][0] *= al0; oacc[mt][nt][1] *= al0;
                oacc[mt][nt][2] *= al1; oacc[mt][nt][3] *= al1;
            }
        }

        // ---- O += P V, P split computed per k-chunk t (bounds register live range) ----
#pragma unroll
        for (int t = 0; t < 4; ++t) {
            uint32_t ph[2][4], pl[2][4];
#pragma unroll
            for (int mt = 0; mt < 2; ++mt) {
                split_pack(sacc[mt][2 * t][0],     sacc[mt][2 * t][1],     ph[mt][0], pl[mt][0]);
                split_pack(sacc[mt][2 * t][2],     sacc[mt][2 * t][3],     ph[mt][1], pl[mt][1]);
                split_pack(sacc[mt][2 * t + 1][0], sacc[mt][2 * t + 1][1], ph[mt][2], pl[mt][2]);
                split_pack(sacc[mt][2 * t + 1][2], sacc[mt][2 * t + 1][3], ph[mt][3], pl[mt][3]);
            }
            uint32_t vh[4][4], vl[4][4];
#pragma unroll
            for (int n2 = 0; n2 < 4; ++n2) {
                uint32_t boff = (uint32_t)((n2 * 16 + browIn) * ROWQ + t * 16 + bcolH) * 2;
                ldsm4(vh[n2][0], vh[n2][1], vh[n2][2], vh[n2][3], vb + boff);
                ldsm4(vl[n2][0], vl[n2][1], vl[n2][2], vl[n2][3], vb + KVARR + boff);
            }
#pragma unroll
            for (int mt = 0; mt < 2; ++mt)
#pragma unroll
                for (int nt = 0; nt < 8; ++nt) {
                    int n2 = nt >> 1, pb = (nt & 1) * 2;
                    mma16816(oacc[mt][nt], ph[mt], vh[n2][pb], vh[n2][pb + 1]);
                }
#pragma unroll
            for (int mt = 0; mt < 2; ++mt)
#pragma unroll
                for (int nt = 0; nt < 8; ++nt) {
                    int n2 = nt >> 1, pb = (nt & 1) * 2;
                    mma16816(oacc[mt][nt], ph[mt], vl[n2][pb], vl[n2][pb + 1]);
                }
#pragma unroll
            for (int mt = 0; mt < 2; ++mt)
#pragma unroll
                for (int nt = 0; nt < 8; ++nt) {
                    int n2 = nt >> 1, pb = (nt & 1) * 2;
                    mma16816(oacc[mt][nt], pl[mt], vh[n2][pb], vh[n2][pb + 1]);
                }
        }
        __syncthreads();
    }

    // ---- epilogue ----
#pragma unroll
    for (int mt = 0; mt < 2; ++mt) {
        const float inv0 = 1.0f / lrow[mt][0], inv1 = 1.0f / lrow[mt][1];
        const int row0 = q0 + warp * 32 + mt * 16 + (lane >> 2);
#pragma unroll
        for (int nt = 0; nt < 8; ++nt) {
            int col = h * HDIM + nt * 8 + (lane & 3) * 2;
            uint32_t hp, lp;
            split_pack(oacc[mt][nt][0] * inv0, oacc[mt][nt][1] * inv0, hp, lp);
            size_t idx0 = (size_t)(b * SS + row0) * DD + col;
            *(uint32_t*)&ahi[idx0] = hp;
            *(uint32_t*)&alo[idx0] = lp;
            split_pack(oacc[mt][nt][2] * inv1, oacc[mt][nt][3] * inv1, hp, lp);
            size_t idx1 = (size_t)(b * SS + row0 + 8) * DD + col;
            *(uint32_t*)&ahi[idx1] = hp;
            *(uint32_t*)&alo[idx1] = lp;
        }
    }
}

// ---------------------------------------------------------------------------
// Launch
// ---------------------------------------------------------------------------
extern "C" void kernel_launch(void* const* d_in, const int* in_sizes, int n_in,
                              void* d_out, int out_size) {
    const float* x     = (const float*)d_in[0];
    const float* w_qkv = (const float*)d_in[1];
    const float* w_out = (const float*)d_in[2];
    float* out = (float*)d_out;

    void* p;
    cudaGetSymbolAddress(&p, g_qkv);  float* qkv = (float*)p;
    __nv_bfloat16 *xhi, *xlo, *whi, *wlo, *ohi, *olo, *ahi, *alo;
    __nv_bfloat16 *qhi, *qlo, *khi, *klo, *vthi, *vtlo;
    cudaGetSymbolAddress(&p, g_xhi); xhi = (__nv_bfloat16*)p;
    cudaGetSymbolAddress(&p, g_xlo); xlo = (__nv_bfloat16*)p;
    cudaGetSymbolAddress(&p, g_whi); whi = (__nv_bfloat16*)p;
    cudaGetSymbolAddress(&p, g_wlo); wlo = (__nv_bfloat16*)p;
    cudaGetSymbolAddress(&p, g_ohi); ohi = (__nv_bfloat16*)p;
    cudaGetSymbolAddress(&p, g_olo); olo = (__nv_bfloat16*)p;
    cudaGetSymbolAddress(&p, g_ahi); ahi = (__nv_bfloat16*)p;
    cudaGetSymbolAddress(&p, g_alo); alo = (__nv_bfloat16*)p;
    cudaGetSymbolAddress(&p, g_qhi); qhi = (__nv_bfloat16*)p;
    cudaGetSymbolAddress(&p, g_qlo); qlo = (__nv_bfloat16*)p;
    cudaGetSymbolAddress(&p, g_khi); khi = (__nv_bfloat16*)p;
    cudaGetSymbolAddress(&p, g_klo); klo = (__nv_bfloat16*)p;
    cudaGetSymbolAddress(&p, g_vthi); vthi = (__nv_bfloat16*)p;
    cudaGetSymbolAddress(&p, g_vtlo); vtlo = (__nv_bfloat16*)p;

    cudaFuncSetAttribute(tc_gemm, cudaFuncAttributeMaxDynamicSharedMemorySize,
                         GT_SMEM_TOTAL);
    cudaFuncSetAttribute(attn_mma, cudaFuncAttributeMaxDynamicSharedMemorySize,
                         ATTN_SMEM);

    // 0) splits
    {
        int n4x = (BB * SS * DD) / 4;
        split_kernel<<<(n4x + 255) / 256, 256>>>(x, xhi, xlo, n4x);
        int n4w = (3 * DD * DD) / 4;
        split_kernel<<<(n4w + 255) / 256, 256>>>(w_qkv, whi, wlo, n4w);
        int n4o = (DD * DD) / 4;
        split_kernel<<<(n4o + 255) / 256, 256>>>(w_out, ohi, olo, n4o);
    }

    // 1) QKV projection
    {
        dim3 grid(3 * DD / 128, (BB * SS) / 128);
        tc_gemm<<<grid, 128, GT_SMEM_TOTAL>>>(xhi, xlo, whi, wlo, qkv, 3 * DD, KDIM);
    }

    // 2) attention preprocessing
    prep_qk<<<4096, 256>>>(qkv, qhi, qlo, khi, klo);
    {
        dim3 grid(SS / 64, HH, BB);
        prep_v<<<grid, 256>>>(qkv, vthi, vtlo);
    }

    // 3) HMMA flash attention
    {
        dim3 grid(SS / BQA, HH, BB);
        attn_mma<<<grid, 256, ATTN_SMEM>>>(qhi, qlo, khi, klo, vthi, vtlo, ahi, alo);
    }

    // 4) output projection
    {
        dim3 grid(DD / 128, (BB * SS) / 128);
        tc_gemm<<<grid, 128, GT_SMEM_TOTAL>>>(ahi, alo, ohi, olo, out, DD, KDIM);
    }
}